// round 1
// baseline (speedup 1.0000x reference)
#include <cuda_runtime.h>
#include <cuda_bf16.h>
#include <math_constants.h>

#define VV 3
#define BB 2
#define CC 16
#define HH 128
#define WW 128
#define DD 32
#define HWSZ (HH*WW)

// Scratch (device globals; no runtime allocation)
__device__ float g_proj[(VV-1)*BB*12];                 // rot(9)+trans(3) per (src view, batch)
__device__ float g_nhwc[(size_t)VV*BB*HWSZ*CC];        // features transposed to (vb, y, x, c)
__device__ float g_cost[(size_t)BB*DD*HWSZ];           // min cost volume (b,d,y,x)

// ---------------------------------------------------------------------------
// K0: projection matrices  proj = M_src @ inv(M_ref)
//     M = [[K @ R^T, (K+I)(-R^T t)],[0,1]]
// ---------------------------------------------------------------------------
__device__ void mat3_inv_d(const double* A, double* o) {
    double c00 = A[4]*A[8]-A[5]*A[7];
    double c01 = A[5]*A[6]-A[3]*A[8];
    double c02 = A[3]*A[7]-A[4]*A[6];
    double det = A[0]*c00 + A[1]*c01 + A[2]*c02;
    double id = 1.0/det;
    o[0]=c00*id;                  o[1]=(A[2]*A[7]-A[1]*A[8])*id; o[2]=(A[1]*A[5]-A[2]*A[4])*id;
    o[3]=c01*id;                  o[4]=(A[0]*A[8]-A[2]*A[6])*id; o[5]=(A[2]*A[3]-A[0]*A[5])*id;
    o[6]=c02*id;                  o[7]=(A[1]*A[6]-A[0]*A[7])*id; o[8]=(A[0]*A[4]-A[1]*A[3])*id;
}

__device__ void build_M(const float* intr, const float* c2w, int vb,
                        double* Afull, double* bfull) {
    double K[9], R[9], t[3];
    #pragma unroll
    for (int i = 0; i < 3; i++) {
        #pragma unroll
        for (int j = 0; j < 3; j++) {
            K[i*3+j] = (double)intr[(vb*3+i)*3+j];
            R[i*3+j] = (double)c2w[(vb*4+i)*4+j];
        }
        t[i] = (double)c2w[(vb*4+i)*4+3];
    }
    // bb = -R^T t
    double bb[3];
    #pragma unroll
    for (int i = 0; i < 3; i++)
        bb[i] = -(R[0*3+i]*t[0] + R[1*3+i]*t[1] + R[2*3+i]*t[2]);
    // Afull = K @ R^T ; bfull = K@bb + bb
    #pragma unroll
    for (int i = 0; i < 3; i++) {
        #pragma unroll
        for (int j = 0; j < 3; j++)
            Afull[i*3+j] = K[i*3+0]*R[j*3+0] + K[i*3+1]*R[j*3+1] + K[i*3+2]*R[j*3+2];
        bfull[i] = K[i*3+0]*bb[0] + K[i*3+1]*bb[1] + K[i*3+2]*bb[2] + bb[i];
    }
}

__global__ void proj_kernel(const float* __restrict__ intr,
                            const float* __restrict__ c2w) {
    int t = threadIdx.x;
    if (t >= (VV-1)*BB) return;
    int v = t / BB + 1;       // src view 1..V-1
    int b = t % BB;

    double As[9], bs[3], Ar[9], br[3];
    build_M(intr, c2w, v*BB + b, As, bs);
    build_M(intr, c2w, 0*BB + b, Ar, br);

    double Ainv[9];
    mat3_inv_d(Ar, Ainv);
    double binv[3];
    #pragma unroll
    for (int i = 0; i < 3; i++)
        binv[i] = -(Ainv[i*3+0]*br[0] + Ainv[i*3+1]*br[1] + Ainv[i*3+2]*br[2]);

    float* P = g_proj + t*12;
    #pragma unroll
    for (int i = 0; i < 3; i++) {
        #pragma unroll
        for (int j = 0; j < 3; j++)
            P[i*3+j] = (float)(As[i*3+0]*Ainv[0*3+j] + As[i*3+1]*Ainv[1*3+j] + As[i*3+2]*Ainv[2*3+j]);
        P[9+i] = (float)(As[i*3+0]*binv[0] + As[i*3+1]*binv[1] + As[i*3+2]*binv[2] + bs[i]);
    }
}

// ---------------------------------------------------------------------------
// K1: transpose features (V,B,C,H,W) -> (vb, y, x, c)
// ---------------------------------------------------------------------------
__global__ void nhwc_kernel(const float* __restrict__ feat) {
    int idx = blockIdx.x * blockDim.x + threadIdx.x;  // over V*B*H*W
    if (idx >= VV*BB*HWSZ) return;
    int pix = idx & (HWSZ-1);
    int vb  = idx >> 14;
    const float* in = feat + (size_t)vb*CC*HWSZ + pix;
    float* o = g_nhwc + (size_t)idx*CC;
    #pragma unroll
    for (int c = 0; c < CC; c++) o[c] = in[(size_t)c*HWSZ];
}

// ---------------------------------------------------------------------------
// K2: homography warp + bilinear sample + cumsum cost + min over views
//     one thread per (b,d,y,x)
// ---------------------------------------------------------------------------
__global__ void warp_cost_kernel(const float* __restrict__ depth_hypo) {
    int idx = blockIdx.x * blockDim.x + threadIdx.x;
    if (idx >= BB*DD*HWSZ) return;
    int x = idx & 127;
    int y = (idx >> 7) & 127;
    int b = idx >> 19;      // (idx>>14)&31 is d, but depth layout matches idx directly

    float depth = depth_hypo[idx];

    const float4* refp = (const float4*)(g_nhwc + ((size_t)b*HWSZ + (y<<7) + x)*CC);
    float4 r0 = refp[0], r1 = refp[1], r2 = refp[2], r3 = refp[3];

    float cum[16];
    #pragma unroll
    for (int c = 0; c < 16; c++) cum[c] = 0.0f;

    const float SXY = (float)WW / (float)(WW-1);
    float fxp = (float)x, fyp = (float)y;
    float cost_min = CUDART_INF_F;

    #pragma unroll
    for (int v = 0; v < VV-1; v++) {
        const float* P = g_proj + (v*BB + b)*12;
        float X = (P[0]*fxp + P[1]*fyp + P[2])*depth + P[9];
        float Y = (P[3]*fxp + P[4]*fyp + P[5])*depth + P[10];
        float Z = (P[6]*fxp + P[7]*fyp + P[8])*depth + P[11];
        float px = (X / Z) * SXY - 0.5f;
        float py = (Y / Z) * SXY - 0.5f;
        float x0f = floorf(px), y0f = floorf(py);
        float tx = px - x0f, ty = py - y0f;
        int x0 = (int)x0f, y0 = (int)y0f;

        float w00 = (1.0f-tx)*(1.0f-ty);
        float w01 = tx*(1.0f-ty);
        float w10 = (1.0f-tx)*ty;
        float w11 = tx*ty;

        const float* sb = g_nhwc + (size_t)((v+1)*BB + b)*HWSZ*CC;

        int xs[4] = {x0, x0+1, x0, x0+1};
        int ys[4] = {y0, y0, y0+1, y0+1};
        float ws[4] = {w00, w01, w10, w11};
        #pragma unroll
        for (int tap = 0; tap < 4; tap++) {
            int xi = xs[tap], yi = ys[tap];
            if ((unsigned)xi < (unsigned)WW && (unsigned)yi < (unsigned)HH) {
                const float4* p = (const float4*)(sb + ((size_t)(yi<<7) + xi)*CC);
                float4 a = p[0], bq = p[1], cq = p[2], dq = p[3];
                float w = ws[tap];
                cum[0]  += w*a.x;  cum[1]  += w*a.y;  cum[2]  += w*a.z;  cum[3]  += w*a.w;
                cum[4]  += w*bq.x; cum[5]  += w*bq.y; cum[6]  += w*bq.z; cum[7]  += w*bq.w;
                cum[8]  += w*cq.x; cum[9]  += w*cq.y; cum[10] += w*cq.z; cum[11] += w*cq.w;
                cum[12] += w*dq.x; cum[13] += w*dq.y; cum[14] += w*dq.z; cum[15] += w*dq.w;
            }
        }

        // cost for this cumsum level: ||ref - cum||_2
        float rv[16] = {r0.x,r0.y,r0.z,r0.w, r1.x,r1.y,r1.z,r1.w,
                        r2.x,r2.y,r2.z,r2.w, r3.x,r3.y,r3.z,r3.w};
        float s = 0.0f;
        #pragma unroll
        for (int c = 0; c < 16; c++) {
            float dlt = rv[c] - cum[c];
            s += dlt*dlt;
        }
        cost_min = fminf(cost_min, sqrtf(s));
    }
    g_cost[idx] = cost_min;
}

// ---------------------------------------------------------------------------
// K3: 5x5 aggregation + softmax over D + depth expectation
//     one thread per (b,y,x)
// ---------------------------------------------------------------------------
__global__ void agg_kernel(const float* __restrict__ depth_hypo,
                           float* __restrict__ out) {
    int idx = blockIdx.x * blockDim.x + threadIdx.x;  // over B*H*W
    if (idx >= BB*HWSZ) return;
    int x = idx & 127;
    int y = (idx >> 7) & 127;
    int b = idx >> 14;

    // center feature vector
    const float4* fcp = (const float4*)(g_nhwc + ((size_t)b*HWSZ + (y<<7) + x)*CC);
    float4 f0 = fcp[0], f1 = fcp[1], f2 = fcp[2], f3 = fcp[3];
    float fc[16] = {f0.x,f0.y,f0.z,f0.w, f1.x,f1.y,f1.z,f1.w,
                    f2.x,f2.y,f2.z,f2.w, f3.x,f3.y,f3.z,f3.w};

    // w_feat[k]: ||f_nb - f_c|| with zero-pad (OOB -> ||f_c||)
    float wfeat[25];
    #pragma unroll
    for (int i = 0; i < 5; i++) {
        #pragma unroll
        for (int j = 0; j < 5; j++) {
            int ny = y + i - 2, nx = x + j - 2;
            float s = 0.0f;
            if ((unsigned)ny < (unsigned)HH && (unsigned)nx < (unsigned)WW) {
                const float4* fnp = (const float4*)(g_nhwc + ((size_t)b*HWSZ + (ny<<7) + nx)*CC);
                float4 a = fnp[0], bq = fnp[1], cq = fnp[2], dq = fnp[3];
                float fn[16] = {a.x,a.y,a.z,a.w, bq.x,bq.y,bq.z,bq.w,
                                cq.x,cq.y,cq.z,cq.w, dq.x,dq.y,dq.z,dq.w};
                #pragma unroll
                for (int c = 0; c < 16; c++) {
                    float dlt = fn[c] - fc[c];
                    s += dlt*dlt;
                }
            } else {
                #pragma unroll
                for (int c = 0; c < 16; c++) s += fc[c]*fc[c];
            }
            wfeat[i*5+j] = (s == 0.0f) ? 0.0f : sqrtf(s);
        }
    }

    const float* dhb = depth_hypo + (size_t)b*DD*HWSZ;
    const float* cvb = g_cost     + (size_t)b*DD*HWSZ;
    int pix = (y<<7) + x;

    // online softmax over D
    float m = -CUDART_INF_F, ssum = 0.0f, tsum = 0.0f;

    for (int d = 0; d < DD; d++) {
        size_t dbase = (size_t)d * HWSZ;
        float dc = dhb[dbase + pix];

        // pass 1: |dnb - dc| for 25 neighbors (OOB -> |0-dc| = dc), find max
        float a[25];
        float amax = -CUDART_INF_F;
        #pragma unroll
        for (int i = 0; i < 5; i++) {
            #pragma unroll
            for (int j = 0; j < 5; j++) {
                int ny = y + i - 2, nx = x + j - 2;
                float dn = 0.0f;
                if ((unsigned)ny < (unsigned)HH && (unsigned)nx < (unsigned)WW)
                    dn = dhb[dbase + (ny<<7) + nx];
                float av = fabsf(dn - dc);
                a[i*5+j] = av;
                amax = fmaxf(amax, av);
            }
        }

        // pass 2: softmax weights * wfeat * cost
        float esum = 0.0f, acc = 0.0f;
        #pragma unroll
        for (int i = 0; i < 5; i++) {
            #pragma unroll
            for (int j = 0; j < 5; j++) {
                int ny = y + i - 2, nx = x + j - 2;
                float e = expf(a[i*5+j] - amax);
                esum += e;
                if ((unsigned)ny < (unsigned)HH && (unsigned)nx < (unsigned)WW) {
                    float cn = cvb[dbase + (ny<<7) + nx];
                    acc += cn * e * wfeat[i*5+j];
                }
            }
        }
        float agg = acc / esum;

        // online softmax update over D
        float nm = fmaxf(m, agg);
        float scale = expf(m - nm);     // first iter: expf(-inf)=0
        float ea = expf(agg - nm);
        ssum = ssum * scale + ea;
        tsum = tsum * scale + ea * dc;
        m = nm;
    }

    out[idx] = tsum / ssum;
}

// ---------------------------------------------------------------------------
extern "C" void kernel_launch(void* const* d_in, const int* in_sizes, int n_in,
                              void* d_out, int out_size) {
    const float* features   = (const float*)d_in[0];  // (3,2,16,128,128)
    const float* intrinsics = (const float*)d_in[1];  // (3,2,3,3)
    const float* cam2world  = (const float*)d_in[2];  // (3,2,4,4)
    const float* depth_hypo = (const float*)d_in[3];  // (2,32,128,128)
    float* out = (float*)d_out;                       // (2,128,128)

    proj_kernel<<<1, 32>>>(intrinsics, cam2world);

    {
        int n = VV*BB*HWSZ;
        nhwc_kernel<<<(n + 255)/256, 256>>>(features);
    }
    {
        int n = BB*DD*HWSZ;
        warp_cost_kernel<<<(n + 255)/256, 256>>>(depth_hypo);
    }
    {
        int n = BB*HWSZ;
        agg_kernel<<<(n + 255)/256, 256>>>(depth_hypo, out);
    }
}

// round 2
// speedup vs baseline: 1.2222x; 1.2222x over previous
#include <cuda_runtime.h>
#include <cuda_bf16.h>
#include <math_constants.h>

#define VV 3
#define BB 2
#define CC 16
#define HH 128
#define WW 128
#define DD 32
#define HWSZ (HH*WW)

// Scratch (device globals; no runtime allocation)
__device__ float g_proj[(VV-1)*BB*12];                 // rot(9)+trans(3) per (src view, batch)
__device__ float g_nhwc[(size_t)VV*BB*HWSZ*CC];        // features transposed to (vb, y, x, c)
__device__ float g_cost[(size_t)BB*DD*HWSZ];           // min cost volume (b,d,y,x)
__device__ float g_wfeat[(size_t)25*BB*HWSZ];          // feature weights [k][b][pix]
__device__ float g_agg[(size_t)BB*DD*HWSZ];            // aggregated costs (b,d,y,x)

// ---------------------------------------------------------------------------
// K0: projection matrices  proj = M_src @ inv(M_ref)
// ---------------------------------------------------------------------------
__device__ void mat3_inv_d(const double* A, double* o) {
    double c00 = A[4]*A[8]-A[5]*A[7];
    double c01 = A[5]*A[6]-A[3]*A[8];
    double c02 = A[3]*A[7]-A[4]*A[6];
    double det = A[0]*c00 + A[1]*c01 + A[2]*c02;
    double id = 1.0/det;
    o[0]=c00*id;                  o[1]=(A[2]*A[7]-A[1]*A[8])*id; o[2]=(A[1]*A[5]-A[2]*A[4])*id;
    o[3]=c01*id;                  o[4]=(A[0]*A[8]-A[2]*A[6])*id; o[5]=(A[2]*A[3]-A[0]*A[5])*id;
    o[6]=c02*id;                  o[7]=(A[1]*A[6]-A[0]*A[7])*id; o[8]=(A[0]*A[4]-A[1]*A[3])*id;
}

__device__ void build_M(const float* intr, const float* c2w, int vb,
                        double* Afull, double* bfull) {
    double K[9], R[9], t[3];
    #pragma unroll
    for (int i = 0; i < 3; i++) {
        #pragma unroll
        for (int j = 0; j < 3; j++) {
            K[i*3+j] = (double)intr[(vb*3+i)*3+j];
            R[i*3+j] = (double)c2w[(vb*4+i)*4+j];
        }
        t[i] = (double)c2w[(vb*4+i)*4+3];
    }
    double bb[3];
    #pragma unroll
    for (int i = 0; i < 3; i++)
        bb[i] = -(R[0*3+i]*t[0] + R[1*3+i]*t[1] + R[2*3+i]*t[2]);
    #pragma unroll
    for (int i = 0; i < 3; i++) {
        #pragma unroll
        for (int j = 0; j < 3; j++)
            Afull[i*3+j] = K[i*3+0]*R[j*3+0] + K[i*3+1]*R[j*3+1] + K[i*3+2]*R[j*3+2];
        bfull[i] = K[i*3+0]*bb[0] + K[i*3+1]*bb[1] + K[i*3+2]*bb[2] + bb[i];
    }
}

__global__ void proj_kernel(const float* __restrict__ intr,
                            const float* __restrict__ c2w) {
    int t = threadIdx.x;
    if (t >= (VV-1)*BB) return;
    int v = t / BB + 1;
    int b = t % BB;

    double As[9], bs[3], Ar[9], br[3];
    build_M(intr, c2w, v*BB + b, As, bs);
    build_M(intr, c2w, 0*BB + b, Ar, br);

    double Ainv[9];
    mat3_inv_d(Ar, Ainv);
    double binv[3];
    #pragma unroll
    for (int i = 0; i < 3; i++)
        binv[i] = -(Ainv[i*3+0]*br[0] + Ainv[i*3+1]*br[1] + Ainv[i*3+2]*br[2]);

    float* P = g_proj + t*12;
    #pragma unroll
    for (int i = 0; i < 3; i++) {
        #pragma unroll
        for (int j = 0; j < 3; j++)
            P[i*3+j] = (float)(As[i*3+0]*Ainv[0*3+j] + As[i*3+1]*Ainv[1*3+j] + As[i*3+2]*Ainv[2*3+j]);
        P[9+i] = (float)(As[i*3+0]*binv[0] + As[i*3+1]*binv[1] + As[i*3+2]*binv[2] + bs[i]);
    }
}

// ---------------------------------------------------------------------------
// K1: transpose features (V,B,C,H,W) -> (vb, y, x, c)
// ---------------------------------------------------------------------------
__global__ void nhwc_kernel(const float* __restrict__ feat) {
    int idx = blockIdx.x * blockDim.x + threadIdx.x;
    if (idx >= VV*BB*HWSZ) return;
    int pix = idx & (HWSZ-1);
    int vb  = idx >> 14;
    const float* in = feat + (size_t)vb*CC*HWSZ + pix;
    float* o = g_nhwc + (size_t)idx*CC;
    #pragma unroll
    for (int c = 0; c < CC; c++) o[c] = in[(size_t)c*HWSZ];
}

// ---------------------------------------------------------------------------
// K2: homography warp + bilinear sample + cumsum cost + min over views
// ---------------------------------------------------------------------------
__global__ void __launch_bounds__(256)
warp_cost_kernel(const float* __restrict__ depth_hypo) {
    int idx = blockIdx.x * blockDim.x + threadIdx.x;
    if (idx >= BB*DD*HWSZ) return;
    int x = idx & 127;
    int y = (idx >> 7) & 127;
    int b = idx >> 19;

    float depth = depth_hypo[idx];

    const float4* refp = (const float4*)(g_nhwc + ((size_t)b*HWSZ + (y<<7) + x)*CC);
    float4 r0 = refp[0], r1 = refp[1], r2 = refp[2], r3 = refp[3];

    float cum[16];
    #pragma unroll
    for (int c = 0; c < 16; c++) cum[c] = 0.0f;

    const float SXY = (float)WW / (float)(WW-1);
    float fxp = (float)x, fyp = (float)y;
    float cost_min = CUDART_INF_F;

    #pragma unroll
    for (int v = 0; v < VV-1; v++) {
        const float* P = g_proj + (v*BB + b)*12;
        float X = (P[0]*fxp + P[1]*fyp + P[2])*depth + P[9];
        float Y = (P[3]*fxp + P[4]*fyp + P[5])*depth + P[10];
        float Z = (P[6]*fxp + P[7]*fyp + P[8])*depth + P[11];
        float px = __fdividef(X, Z) * SXY - 0.5f;
        float py = __fdividef(Y, Z) * SXY - 0.5f;
        float x0f = floorf(px), y0f = floorf(py);
        float tx = px - x0f, ty = py - y0f;
        int x0 = (int)x0f, y0 = (int)y0f;

        float w00 = (1.0f-tx)*(1.0f-ty);
        float w01 = tx*(1.0f-ty);
        float w10 = (1.0f-tx)*ty;
        float w11 = tx*ty;

        const float* sb = g_nhwc + (size_t)((v+1)*BB + b)*HWSZ*CC;

        int xs[4] = {x0, x0+1, x0, x0+1};
        int ys[4] = {y0, y0, y0+1, y0+1};
        float ws[4] = {w00, w01, w10, w11};
        #pragma unroll
        for (int tap = 0; tap < 4; tap++) {
            int xi = xs[tap], yi = ys[tap];
            if ((unsigned)xi < (unsigned)WW && (unsigned)yi < (unsigned)HH) {
                const float4* p = (const float4*)(sb + ((size_t)(yi<<7) + xi)*CC);
                float4 a = p[0], bq = p[1], cq = p[2], dq = p[3];
                float w = ws[tap];
                cum[0]  += w*a.x;  cum[1]  += w*a.y;  cum[2]  += w*a.z;  cum[3]  += w*a.w;
                cum[4]  += w*bq.x; cum[5]  += w*bq.y; cum[6]  += w*bq.z; cum[7]  += w*bq.w;
                cum[8]  += w*cq.x; cum[9]  += w*cq.y; cum[10] += w*cq.z; cum[11] += w*cq.w;
                cum[12] += w*dq.x; cum[13] += w*dq.y; cum[14] += w*dq.z; cum[15] += w*dq.w;
            }
        }

        float rv[16] = {r0.x,r0.y,r0.z,r0.w, r1.x,r1.y,r1.z,r1.w,
                        r2.x,r2.y,r2.z,r2.w, r3.x,r3.y,r3.z,r3.w};
        float s = 0.0f;
        #pragma unroll
        for (int c = 0; c < 16; c++) {
            float dlt = rv[c] - cum[c];
            s += dlt*dlt;
        }
        cost_min = fminf(cost_min, sqrtf(s));
    }
    g_cost[idx] = cost_min;
}

// ---------------------------------------------------------------------------
// K3a: feature weights per (k, b, pix):  wfeat = ||f_nb - f_c||
//      layout g_wfeat[k][b][pix] for coalesced reads in K3b
// ---------------------------------------------------------------------------
__global__ void __launch_bounds__(256)
wfeat_kernel() {
    int idx = blockIdx.x * blockDim.x + threadIdx.x;   // over 25*B*HWSZ
    if (idx >= 25*BB*HWSZ) return;
    int pix = idx & (HWSZ-1);
    int b   = (idx >> 14) & (BB-1);
    int k   = idx >> 15;
    int x = pix & 127;
    int y = pix >> 7;
    int ny = y + k/5 - 2, nx = x + k%5 - 2;

    float w = 0.0f;
    if ((unsigned)ny < (unsigned)HH && (unsigned)nx < (unsigned)WW) {
        const float4* fcp = (const float4*)(g_nhwc + ((size_t)b*HWSZ + pix)*CC);
        const float4* fnp = (const float4*)(g_nhwc + ((size_t)b*HWSZ + (ny<<7) + nx)*CC);
        float s = 0.0f;
        #pragma unroll
        for (int q = 0; q < 4; q++) {
            float4 a = fcp[q], c = fnp[q];
            float d0 = a.x-c.x, d1 = a.y-c.y, d2 = a.z-c.z, d3 = a.w-c.w;
            s += d0*d0 + d1*d1 + d2*d2 + d3*d3;
        }
        w = sqrtf(s);
    }
    g_wfeat[idx] = w;
}

// ---------------------------------------------------------------------------
// K3b: per-(b,d,pix) neighborhood aggregation with depth softmax weights
// ---------------------------------------------------------------------------
__global__ void __launch_bounds__(256)
aggd_kernel(const float* __restrict__ depth_hypo) {
    int idx = blockIdx.x * blockDim.x + threadIdx.x;   // over B*D*HWSZ
    if (idx >= BB*DD*HWSZ) return;
    int pix = idx & (HWSZ-1);
    int x = pix & 127;
    int y = pix >> 7;
    int b = idx >> 19;

    const float* dsl = depth_hypo + (idx & ~(HWSZ-1)); // (b,d) depth slice
    const float* csl = g_cost     + (idx & ~(HWSZ-1)); // (b,d) cost slice
    const float* wfb = g_wfeat + (size_t)b*HWSZ + pix;

    float dc = dsl[pix];
    float esum = 0.0f, acc = 0.0f;

    #pragma unroll
    for (int k = 0; k < 25; k++) {
        int ny = y + k/5 - 2, nx = x + k%5 - 2;
        bool inb = (unsigned)ny < (unsigned)HH && (unsigned)nx < (unsigned)WW;
        int np = (ny<<7) + nx;
        float dn = inb ? dsl[np] : 0.0f;
        float e = __expf(fabsf(dn - dc));   // args in [0,~9]: no overflow, no shift needed
        esum += e;
        if (inb) {
            float cn = csl[np];
            float wf = wfb[(size_t)k * (BB*HWSZ)];
            acc += cn * e * wf;
        }
    }
    g_agg[idx] = __fdividef(acc, esum);
}

// ---------------------------------------------------------------------------
// K3c: softmax over D + depth expectation, per (b,pix)
// ---------------------------------------------------------------------------
__global__ void __launch_bounds__(128)
expect_kernel(const float* __restrict__ depth_hypo,
              float* __restrict__ out) {
    int idx = blockIdx.x * blockDim.x + threadIdx.x;   // over B*HWSZ
    if (idx >= BB*HWSZ) return;
    int pix = idx & (HWSZ-1);
    int b   = idx >> 14;

    const float* ab = g_agg     + (size_t)b*DD*HWSZ + pix;
    const float* db = depth_hypo + (size_t)b*DD*HWSZ + pix;

    float ag[DD], dv[DD];
    float m = -CUDART_INF_F;
    #pragma unroll
    for (int d = 0; d < DD; d++) {
        ag[d] = ab[(size_t)d*HWSZ];
        dv[d] = db[(size_t)d*HWSZ];
        m = fmaxf(m, ag[d]);
    }
    float ssum = 0.0f, tsum = 0.0f;
    #pragma unroll
    for (int d = 0; d < DD; d++) {
        float e = __expf(ag[d] - m);
        ssum += e;
        tsum += e * dv[d];
    }
    out[idx] = __fdividef(tsum, ssum);
}

// ---------------------------------------------------------------------------
extern "C" void kernel_launch(void* const* d_in, const int* in_sizes, int n_in,
                              void* d_out, int out_size) {
    const float* features   = (const float*)d_in[0];  // (3,2,16,128,128)
    const float* intrinsics = (const float*)d_in[1];  // (3,2,3,3)
    const float* cam2world  = (const float*)d_in[2];  // (3,2,4,4)
    const float* depth_hypo = (const float*)d_in[3];  // (2,32,128,128)
    float* out = (float*)d_out;                       // (2,128,128)

    proj_kernel<<<1, 32>>>(intrinsics, cam2world);

    {
        int n = VV*BB*HWSZ;
        nhwc_kernel<<<(n + 255)/256, 256>>>(features);
    }
    {
        int n = BB*DD*HWSZ;
        warp_cost_kernel<<<(n + 255)/256, 256>>>(depth_hypo);
    }
    {
        int n = 25*BB*HWSZ;
        wfeat_kernel<<<(n + 255)/256, 256>>>();
    }
    {
        int n = BB*DD*HWSZ;
        aggd_kernel<<<(n + 255)/256, 256>>>(depth_hypo);
    }
    {
        int n = BB*HWSZ;
        expect_kernel<<<(n + 127)/128, 128>>>(depth_hypo, out);
    }
}